// round 7
// baseline (speedup 1.0000x reference)
#include <cuda_runtime.h>
#include <cstdint>

typedef unsigned long long ull;

#define T_STEPS 2048
#define BATCH   64
#define DIN     256
#define HID     256
#define GDIM    1024   // 4*HID gate columns
#define ODIM    128

#define NCHUNK  8      // CTAs per cluster (= per batch group)
#define NGROUP  16     // batch groups
#define BLOC    4      // batch elements per group
#define GCH     128    // permuted gate columns per CTA

// ---------------- static device scratch (no allocation allowed) -------------
__device__ float g_xproj[(size_t)T_STEPS * BATCH * GDIM];  // 512 MB
__device__ float g_WdT[GDIM * DIN];    // permuted [g'][d]
__device__ float g_WhT[GDIM * HID];    // permuted [g'][k]
__device__ float g_b4[GDIM];
__device__ float g_h[BATCH * HID];     // final hidden state h_T

// ---------------- helpers ---------------------------------------------------
union F2U { float2 f; ull u; };
__device__ __forceinline__ ull pack2(float x, float y) { F2U t; t.f = make_float2(x, y); return t.u; }
__device__ __forceinline__ float2 unpack2(ull v) { F2U t; t.u = v; return t.f; }

__device__ __forceinline__ void ffma2(ull &acc, ull a, ull b) {
    asm("fma.rn.f32x2 %0, %1, %2, %0;" : "+l"(acc) : "l"(a), "l"(b));
}
__device__ __forceinline__ float sigf(float x) {
    return __fdividef(1.f, 1.f + __expf(-x));
}
__device__ __forceinline__ float tanhfast(float x) {
    return 1.f - __fdividef(2.f, __expf(2.f * x) + 1.f);
}
__device__ __forceinline__ uint32_t smem_u32(const void* p) {
    return (uint32_t)__cvta_generic_to_shared(p);
}

// ---------------- kernel 0: permute weights ---------------------------------
__global__ void prep_kernel(const float* __restrict__ Wf, const float* __restrict__ Wi,
                            const float* __restrict__ Wc, const float* __restrict__ Wo,
                            const float* __restrict__ bf, const float* __restrict__ bi,
                            const float* __restrict__ bc, const float* __restrict__ bo) {
    int gp = blockIdx.x;          // permuted gate column g' = 4n + gate
    int d  = threadIdx.x;         // 0..255
    int gate = gp & 3, n = gp >> 2;
    const float* W = (gate == 0) ? Wf : (gate == 1) ? Wi : (gate == 2) ? Wc : Wo;
    const float* B = (gate == 0) ? bf : (gate == 1) ? bi : (gate == 2) ? bc : bo;
    g_WdT[gp * DIN + d] = W[n * (DIN + HID) + d];
    g_WhT[gp * HID + d] = W[n * (DIN + HID) + DIN + d];
    if (d == 0) g_b4[gp] = B[n];
}

// ---------------- kernel 1: x_proj GEMM (f32x2 packed FMA) ------------------
__global__ __launch_bounds__(256) void xproj_kernel(const float* __restrict__ inputs) {
    __shared__ float As[32][136];
    __shared__ float Bs[32][68];
    int tid   = threadIdx.x;
    int Rbase = blockIdx.x * 128;
    int Gbase = blockIdx.y * 64;
    int tg = tid & 15;
    int tr = tid >> 4;

    ull acc[4][4];
    #pragma unroll
    for (int gi = 0; gi < 4; gi++)
        #pragma unroll
        for (int rp = 0; rp < 4; rp++) acc[gi][rp] = 0ull;

    for (int k0 = 0; k0 < DIN; k0 += 32) {
        #pragma unroll
        for (int i = 0; i < 4; i++) {
            int s = tid + i * 256;
            int row = s >> 3, d4 = s & 7;
            int r = Rbase + row;
            int b = r & 63, t = r >> 6;
            const float4 v = *(const float4*)&inputs[((size_t)b * T_STEPS + t) * DIN + k0 + d4 * 4];
            As[d4 * 4 + 0][row] = v.x; As[d4 * 4 + 1][row] = v.y;
            As[d4 * 4 + 2][row] = v.z; As[d4 * 4 + 3][row] = v.w;
        }
        #pragma unroll
        for (int i = 0; i < 2; i++) {
            int s = tid + i * 256;
            int gr = s >> 3, d4 = s & 7;
            const float4 v = *(const float4*)&g_WdT[(size_t)(Gbase + gr) * DIN + k0 + d4 * 4];
            Bs[d4 * 4 + 0][gr] = v.x; Bs[d4 * 4 + 1][gr] = v.y;
            Bs[d4 * 4 + 2][gr] = v.z; Bs[d4 * 4 + 3][gr] = v.w;
        }
        __syncthreads();
        #pragma unroll
        for (int k = 0; k < 32; k++) {
            ulonglong2 a01 = *(const ulonglong2*)&As[k][tr * 8];
            ulonglong2 a23 = *(const ulonglong2*)&As[k][tr * 8 + 4];
            ull ap[4] = { a01.x, a01.y, a23.x, a23.y };
            const float4 bv = *(const float4*)&Bs[k][tg * 4];
            ull bs0 = pack2(bv.x, bv.x), bs1 = pack2(bv.y, bv.y);
            ull bs2 = pack2(bv.z, bv.z), bs3 = pack2(bv.w, bv.w);
            #pragma unroll
            for (int rp = 0; rp < 4; rp++) {
                ffma2(acc[0][rp], ap[rp], bs0);
                ffma2(acc[1][rp], ap[rp], bs1);
                ffma2(acc[2][rp], ap[rp], bs2);
                ffma2(acc[3][rp], ap[rp], bs3);
            }
        }
        __syncthreads();
    }
    int g0 = Gbase + tg * 4;
    float4 bias = *(const float4*)&g_b4[g0];
    #pragma unroll
    for (int rp = 0; rp < 4; rp++) {
        float2 p0 = unpack2(acc[0][rp]), p1 = unpack2(acc[1][rp]);
        float2 p2 = unpack2(acc[2][rp]), p3 = unpack2(acc[3][rp]);
        size_t r0 = (size_t)(Rbase + tr * 8 + rp * 2);
        *(float4*)&g_xproj[r0 * GDIM + g0] =
            make_float4(p0.x + bias.x, p1.x + bias.y, p2.x + bias.z, p3.x + bias.w);
        *(float4*)&g_xproj[(r0 + 1) * GDIM + g0] =
            make_float4(p0.y + bias.x, p1.y + bias.y, p2.y + bias.z, p3.y + bias.w);
    }
}

// ---------------- kernel 2: persistent LSTM scan (clustered DSMEM) ----------
// 16 clusters of 8 CTAs. Cluster = one batch group (4 batches). Each CTA owns
// 128 permuted gate columns. h is exchanged via st.shared::cluster into every
// cluster CTA's smem; completion via 2 alternating cluster mbarriers.
__global__ __launch_bounds__(256) __cluster_dims__(NCHUNK, 1, 1)
void scan_kernel() {
    __shared__ __align__(16) ull   hsm[2][BLOC][HID / 2];  // h pairs, dbl-buffered
    __shared__ __align__(16) float partial[4][BLOC][GCH + 4];
    __shared__ __align__(16) ull   xps2[256];
    __shared__ float cs[BLOC * 32];
    __shared__ __align__(8) ull    mbar[2];

    int tid = threadIdx.x;
    int c   = blockIdx.x & (NCHUNK - 1);    // cluster rank
    int gb  = blockIdx.x / NCHUNK;          // batch group
    int gl  = tid & 63;                     // gate-col lane (cols gl, gl+64)
    int kc  = tid >> 6;                     // k-chunk of 64 (4 chunks)

    // Wh slice -> registers, k-paired for f32x2 (128 weights/thread)
    ull wh[2][32];
    #pragma unroll
    for (int gi = 0; gi < 2; gi++) {
        int gp = c * GCH + gl + gi * 64;
        const float4* src = (const float4*)&g_WhT[(size_t)gp * HID + kc * 64];
        #pragma unroll
        for (int j = 0; j < 16; j++) {
            float4 v = src[j];
            wh[gi][2 * j]     = pack2(v.x, v.y);
            wh[gi][2 * j + 1] = pack2(v.z, v.w);
        }
    }
    // h(0)=0, c(0)=0 ; init mbarriers
    for (int i = tid; i < BLOC * HID / 2; i += 256) hsm[0][0][i] = 0ull;
    if (tid < BLOC * 32) cs[tid] = 0.f;
    if (tid == 0) {
        uint32_t mb0 = smem_u32(&mbar[0]);
        asm volatile("mbarrier.init.shared.b64 [%0], %1;" :: "r"(mb0), "r"(NCHUNK) : "memory");
        asm volatile("mbarrier.init.shared.b64 [%0], %1;" :: "r"(mb0 + 8), "r"(NCHUNK) : "memory");
    }
    // x_proj prefetch: thread covers (b, 2 gate cols)
    int bl  = tid >> 6;
    int gl2 = (tid & 63) * 2;
    size_t xbase = (size_t)(gb * BLOC + bl) * GDIM + c * GCH + gl2;
    ull xpre = *(const ull*)&g_xproj[xbase];
    __syncthreads();
    asm volatile("barrier.cluster.arrive.aligned;" ::: "memory");
    asm volatile("barrier.cluster.wait.aligned;" ::: "memory");

    for (int t = 0; t < T_STEPS; t++) {
        // publish x_proj(t); prefetch x_proj(t+1)
        xps2[tid] = xpre;
        if (t + 1 < T_STEPS)
            xpre = *(const ull*)&g_xproj[(size_t)(t + 1) * (BATCH * GDIM) + xbase];

        int sr = t & 1;
        // recurrent GEMM: 2 gate-cols x 4 batches over 64-k chunk
        ull acc[2][4];
        #pragma unroll
        for (int gi = 0; gi < 2; gi++)
            #pragma unroll
            for (int b = 0; b < 4; b++) acc[gi][b] = 0ull;
        #pragma unroll
        for (int k4 = 0; k4 < 16; k4++) {               // 2 k-pairs per iter
            int ka = kc * 32 + k4 * 2;
            ulonglong2 hb[4];
            #pragma unroll
            for (int b = 0; b < 4; b++)
                hb[b] = *(const ulonglong2*)&hsm[sr][b][ka];
            #pragma unroll
            for (int b = 0; b < 4; b++) {
                ffma2(acc[0][b], wh[0][2 * k4],     hb[b].x);
                ffma2(acc[1][b], wh[1][2 * k4],     hb[b].x);
                ffma2(acc[0][b], wh[0][2 * k4 + 1], hb[b].y);
                ffma2(acc[1][b], wh[1][2 * k4 + 1], hb[b].y);
            }
        }
        #pragma unroll
        for (int b = 0; b < 4; b++) {
            float2 p0 = unpack2(acc[0][b]);
            float2 p1 = unpack2(acc[1][b]);
            partial[kc][b][gl]      = p0.x + p0.y;
            partial[kc][b][gl + 64] = p1.x + p1.y;
        }
        __syncthreads();

        int sw = (t + 1) & 1;
        bool last = (t == T_STEPS - 1);
        // gate reduce + nonlinearity + h broadcast (128 threads: b x n)
        if (tid < 128) {
            int b = tid >> 5, n = tid & 31;
            const float* xpsf = (const float*)xps2;
            float4 v = *(const float4*)&xpsf[b * GCH + 4 * n];
            #pragma unroll
            for (int kk = 0; kk < 4; kk++) {
                float4 p = *(const float4*)&partial[kk][b][4 * n];
                v.x += p.x; v.y += p.y; v.z += p.z; v.w += p.w;
            }
            float f  = sigf(v.x);
            float ii = sigf(v.y);
            float ch = tanhfast(v.z);
            float oo = sigf(v.w);
            float cn = f * cs[tid] + ii * ch;
            cs[tid] = cn;
            float hn = oo * tanhfast(cn);

            // pack 4 consecutive n into float4 on lanes n%4==0
            int lane = tid & 31;
            int lb = lane & ~3;
            float h1 = __shfl_sync(0xffffffffu, hn, lb + 1);
            float h2 = __shfl_sync(0xffffffffu, hn, lb + 2);
            float h3 = __shfl_sync(0xffffffffu, hn, lb + 3);
            if ((lane & 3) == 0) {
                int kh = c * 32 + n;                    // multiple of 4
                if (!last) {
                    uint32_t dst = smem_u32(&hsm[sw][b][0]) + (uint32_t)kh * 4u;
                    #pragma unroll
                    for (int r = 0; r < NCHUNK; r++) {
                        uint32_t ra;
                        asm volatile("mapa.shared::cluster.u32 %0, %1, %2;"
                                     : "=r"(ra) : "r"(dst), "r"(r));
                        asm volatile("st.shared::cluster.v4.f32 [%0], {%1,%2,%3,%4};"
                                     :: "r"(ra), "f"(hn), "f"(h1), "f"(h2), "f"(h3)
                                     : "memory");
                    }
                } else {
                    *(float4*)&g_h[(gb * BLOC + b) * HID + kh] =
                        make_float4(hn, h1, h2, h3);
                }
            }
        }
        __syncthreads();   // all remote stores precede the arrives (cumulative)

        if (!last) {
            uint32_t mb = smem_u32(&mbar[sw]);
            if (tid < NCHUNK) {
                uint32_t ra;
                asm volatile("mapa.shared::cluster.u32 %0, %1, %2;"
                             : "=r"(ra) : "r"(mb), "r"(tid));
                asm volatile("mbarrier.arrive.release.cluster.shared::cluster.b64 _, [%0];"
                             :: "r"(ra) : "memory");
            }
            unsigned parity = (unsigned)((t >> 1) & 1);
            unsigned done;
            asm volatile(
                "{\n\t.reg .pred p;\n\t"
                "mbarrier.try_wait.parity.acquire.cluster.shared::cta.b64 p, [%1], %2;\n\t"
                "selp.b32 %0, 1, 0, p;\n\t}"
                : "=r"(done) : "r"(mb), "r"(parity) : "memory");
            if (!done) {
                asm volatile(
                    "{\n\t.reg .pred P1;\n\t"
                    "WL_%=:\n\t"
                    "mbarrier.try_wait.parity.acquire.cluster.shared::cta.b64 P1, [%0], %1, 0x989680;\n\t"
                    "@P1 bra.uni WD_%=;\n\t"
                    "bra.uni WL_%=;\n\t"
                    "WD_%=:\n\t}"
                    :: "r"(mb), "r"(parity) : "memory");
            }
        }
    }
}

// ---------------- kernel 3: output projection -------------------------------
__global__ __launch_bounds__(128) void out_kernel(const float* __restrict__ W_out,
                                                  const float* __restrict__ b_out,
                                                  float* __restrict__ out) {
    __shared__ float h[HID];
    int b = blockIdx.x, o = threadIdx.x;
    const float* hrow = &g_h[b * HID];
    h[o] = hrow[o];
    h[o + 128] = hrow[o + 128];
    __syncthreads();
    float s = b_out[o];
    const float* w = &W_out[o * HID];
    #pragma unroll 8
    for (int k = 0; k < HID; k++) s += h[k] * w[k];
    out[b * ODIM + o] = s;
}

// ---------------- launch -----------------------------------------------------
extern "C" void kernel_launch(void* const* d_in, const int* in_sizes, int n_in,
                              void* d_out, int out_size) {
    const float* inputs = (const float*)d_in[0];
    const float* W_f = (const float*)d_in[1];
    const float* b_f = (const float*)d_in[2];
    const float* W_i = (const float*)d_in[3];
    const float* b_i = (const float*)d_in[4];
    const float* W_c = (const float*)d_in[5];
    const float* b_c = (const float*)d_in[6];
    const float* W_o = (const float*)d_in[7];
    const float* b_o = (const float*)d_in[8];
    const float* W_out = (const float*)d_in[9];
    const float* b_out = (const float*)d_in[10];
    float* out = (float*)d_out;

    prep_kernel<<<GDIM, 256>>>(W_f, W_i, W_c, W_o, b_f, b_i, b_c, b_o);
    xproj_kernel<<<dim3((T_STEPS * BATCH) / 128, GDIM / 64), 256>>>(inputs);
    scan_kernel<<<NGROUP * NCHUNK, 256>>>();
    out_kernel<<<BATCH, 128>>>(W_out, b_out, out);
}